// round 3
// baseline (speedup 1.0000x reference)
#include <cuda_runtime.h>

// Problem constants
#define NB 128   // batch
#define CC 64    // in channels
#define TT 128   // time
#define VV 25    // vertices
#define RR 8     // rel channels
#define OC 64    // out channels

// ---- scratch (device globals: no allocation allowed) ----
__device__ float g_xm[NB * CC * VV];                // mean over T   (819 KB)
__device__ float g_top[(size_t)NB * OC * VV * VV];  // top tensor (20.5 MB)

// ---- packed fp32x2 helpers (Blackwell FFMA2 path) ----
union f2u {
    float2 f;
    unsigned long long u;
};

__device__ __forceinline__ unsigned long long ffma2(
    unsigned long long a, unsigned long long b, unsigned long long c) {
    unsigned long long d;
    asm("fma.rn.f32x2 %0, %1, %2, %3;" : "=l"(d) : "l"(a), "l"(b), "l"(c));
    return d;
}

// ============================================================
// K1: xm[n,c,v] = mean_t x[n,c,t,v]
// one CTA per (n,c); float4 coalesced stage + deterministic reduction
// ============================================================
__global__ void k_mean(const float* __restrict__ x) {
    __shared__ float xs[TT * VV];        // 3200 floats
    __shared__ float part[4][VV];
    const int b = blockIdx.x;            // n*CC + c
    const float4* px4 = reinterpret_cast<const float4*>(x + (size_t)b * (TT * VV));
    float4* xs4 = reinterpret_cast<float4*>(xs);
    const int tid = threadIdx.x;         // 128 threads

    #pragma unroll
    for (int i = tid; i < TT * VV / 4; i += 128) xs4[i] = px4[i];
    __syncthreads();

    if (tid < 100) {
        const int v = tid % VV, q = tid / VV;   // q in [0,4)
        float s = 0.f;
        #pragma unroll
        for (int t = 0; t < 32; t++) s += xs[(q * 32 + t) * VV + v];
        part[q][v] = s;
    }
    __syncthreads();
    if (tid < VV) {
        float s = (part[0][tid] + part[1][tid]) + (part[2][tid] + part[3][tid]);
        g_xm[b * VV + tid] = s * (1.0f / TT);
    }
}

// ============================================================
// K2: top[n,o,u,v] = ALPHA*(sum_r w4[o,r]*tanh(x1[n,r,u]-x2[n,r,v]) + b4[o]) + A[u,v]
// one CTA per n
// ============================================================
__global__ void k_top(const float* __restrict__ A,
                      const float* __restrict__ w1, const float* __restrict__ b1,
                      const float* __restrict__ w2, const float* __restrict__ b2,
                      const float* __restrict__ w4, const float* __restrict__ b4) {
    __shared__ float xm_s[CC * VV];      // 1600
    __shared__ float x1_s[RR * VV];      // 200
    __shared__ float x2_s[RR * VV];      // 200
    __shared__ float d_s[RR * VV * VV];  // 5000
    __shared__ float w4_s[OC * RR];      // 512
    __shared__ float A_s[VV * VV];       // 625
    const int n = blockIdx.x;
    const int tid = threadIdx.x;         // 256 threads

    for (int i = tid; i < CC * VV; i += 256) xm_s[i] = g_xm[n * CC * VV + i];
    for (int i = tid; i < OC * RR; i += 256) w4_s[i] = w4[i];
    for (int i = tid; i < VV * VV; i += 256) A_s[i] = A[i];
    __syncthreads();

    if (tid < RR * VV) {
        const int r = tid / VV, v = tid % VV;
        float a1 = b1[r], a2 = b2[r];
        #pragma unroll 8
        for (int c = 0; c < CC; c++) {
            const float xv = xm_s[c * VV + v];
            a1 = fmaf(w1[r * CC + c], xv, a1);
            a2 = fmaf(w2[r * CC + c], xv, a2);
        }
        x1_s[tid] = a1;
        x2_s[tid] = a2;
    }
    __syncthreads();

    for (int i = tid; i < RR * VV * VV; i += 256) {
        const int r = i / (VV * VV), rem = i % (VV * VV);
        const int u = rem / VV, v = rem % VV;
        d_s[i] = tanhf(x1_s[r * VV + u] - x2_s[r * VV + v]);
    }
    __syncthreads();

    for (int p = tid; p < VV * VV; p += 256) {
        float dr[RR];
        #pragma unroll
        for (int r = 0; r < RR; r++) dr[r] = d_s[r * VV * VV + p];
        const float av = A_s[p];
        float* dst = g_top + (size_t)n * OC * VV * VV + p;
        #pragma unroll 4
        for (int o = 0; o < OC; o++) {
            float s = b4[o];
            #pragma unroll
            for (int r = 0; r < RR; r++) s = fmaf(w4_s[o * RR + r], dr[r], s);
            dst[o * VV * VV] = s * 1.0f /*ALPHA*/ + av;
        }
    }
}

// ============================================================
// K3 (hot): per (n, o-group of 16):
//   x3[o,t,v] = b3[o] + sum_c w3[o,c]*x[n,c,t,v]       (Phase B, FFMA2)
//   out[n,o,t,u] = sum_v top[n,o,u,v]*x3[o,t,v]        (Phase C, FFMA2)
// ============================================================
#define OO_CTA 16          // o's per CTA (4 groups)
#define TTILE  8           // timesteps per tile
#define JD     (TTILE * VV)   // 200 columns; 100 f32x2 pairs
#define NPAIR  (JD / 2)       // 100

// dynamic smem layout (in floats):
#define OFF_TOP  0                         // 16*625 = 10000
#define OFF_W3D  10000                     // duplicated w3: 16*64 float2 = 2048 floats (8B aligned)
#define OFF_B3   12048                     // 16
#define OFF_X    12064                     // 64*200 = 12800 (16B aligned)
#define OFF_X3T  24864                     // 16*200 = 3200  (16B aligned)
#define SMEM_FLOATS 28064
#define SMEM_BYTES  (SMEM_FLOATS * 4)      // 112256 B -> 2 CTAs/SM

__global__ __launch_bounds__(256, 2)
void k_main(const float* __restrict__ x, const float* __restrict__ w3,
            const float* __restrict__ b3, float* __restrict__ out) {
    extern __shared__ float sm[];
    float*  top_s = sm + OFF_TOP;
    float2* w3d_s = reinterpret_cast<float2*>(sm + OFF_W3D);
    float*  b3_s  = sm + OFF_B3;
    float*  x_s   = sm + OFF_X;
    float*  x3t_s = sm + OFF_X3T;

    const int og  = blockIdx.x;           // 0..3
    const int n   = blockIdx.y;           // 0..127
    const int tid = threadIdx.x;          // 256
    const int obase = og * OO_CTA;

    // per-CTA constants into smem
    const float* ptop = g_top + ((size_t)n * OC + obase) * (VV * VV);
    for (int i = tid; i < OO_CTA * VV * VV; i += 256) top_s[i] = ptop[i];
    for (int i = tid; i < OO_CTA * CC; i += 256) {
        const float w = w3[obase * CC + i];
        w3d_s[i] = make_float2(w, w);     // duplicated for FFMA2 broadcast operand
    }
    if (tid < OO_CTA) b3_s[tid] = b3[obase + tid];

    const int ty   = tid >> 6;            // 0..3  -> 4 o's each (warp-uniform)
    const int tx   = tid & 63;            // 0..63 -> pair columns
    const int warp = tid >> 5;            // 0..7  -> 2 o's each in Phase C
    const int lane = tid & 31;
    const int u    = (lane < VV) ? lane : 0;

    // Phase B pair assignment: pairs p0 = tx, p1 = tx+64 (valid if < 100)
    const int  p0 = tx;
    const bool v1 = (tx + 64) < NPAIR;
    const int  p1 = v1 ? (tx + 64) : 0;

    // Precompute x3t scatter offsets (x3t[oo][v][tt], oo added later)
    int soff[4];
    {
        const int j0 = 2 * p0, j1 = 2 * p1;
        soff[0] = (j0 % VV) * TTILE + (j0 / VV);
        soff[1] = ((j0 + 1) % VV) * TTILE + ((j0 + 1) / VV);
        soff[2] = (j1 % VV) * TTILE + (j1 / VV);
        soff[3] = ((j1 + 1) % VV) * TTILE + ((j1 + 1) / VV);
    }

    const float4* gx4 = reinterpret_cast<const float4*>(x) + (size_t)n * (CC * TT * VV / 4);
    // per-c row stride in float4: TT*VV/4 = 800

    __syncthreads();   // top/w3/b3 ready

    for (int t0 = 0; t0 < TT; t0 += TTILE) {
        // ---- Phase A: load x tile [64 c][200 j] as float4 (t0*25 % 4 == 0) ----
        const int tstart4 = (t0 * VV) >> 2;
        for (int i = tid; i < CC * (JD / 4); i += 256) {
            const int c = i / (JD / 4);
            const int q = i % (JD / 4);
            reinterpret_cast<float4*>(x_s)[c * (JD / 4) + q] = gx4[c * 800 + tstart4 + q];
        }
        __syncthreads();   // x_s ready; also guarantees prior Phase C done

        // ---- Phase B: x3 (4 o x 2 f32x2 pairs, FFMA2) ----
        unsigned long long acc2[4][2];
        #pragma unroll
        for (int i = 0; i < 4; i++) {
            f2u bb; const float b = b3_s[ty * 4 + i];
            bb.f = make_float2(b, b);
            acc2[i][0] = bb.u;
            acc2[i][1] = bb.u;
        }
        #pragma unroll 4
        for (int c = 0; c < CC; c++) {
            f2u xv0, xv1;
            xv0.f = *reinterpret_cast<const float2*>(x_s + c * JD + 2 * p0);
            xv1.f = *reinterpret_cast<const float2*>(x_s + c * JD + 2 * p1);
            #pragma unroll
            for (int i = 0; i < 4; i++) {
                f2u wv; wv.f = w3d_s[(ty * 4 + i) * CC + c];   // broadcast LDS.64
                acc2[i][0] = ffma2(xv0.u, wv.u, acc2[i][0]);
                acc2[i][1] = ffma2(xv1.u, wv.u, acc2[i][1]);
            }
        }
        // store transposed: x3t[oo][v][tt] so Phase C reads tt-contiguous
        #pragma unroll
        for (int i = 0; i < 4; i++) {
            const int oo = ty * 4 + i;
            float* dst = x3t_s + oo * JD;
            f2u a0, a1; a0.u = acc2[i][0]; a1.u = acc2[i][1];
            dst[soff[0]] = a0.f.x;
            dst[soff[1]] = a0.f.y;
            if (v1) {
                dst[soff[2]] = a1.f.x;
                dst[soff[3]] = a1.f.y;
            }
        }
        __syncthreads();   // x3t ready

        // ---- Phase C: out[o,t,u] = sum_v top[o,u,v]*x3[o,t,v] (FFMA2 over tt pairs) ----
        #pragma unroll
        for (int k = 0; k < 2; k++) {
            const int oo = warp * 2 + k;
            unsigned long long oa2[4] = {0ull, 0ull, 0ull, 0ull};
            const float* tp = top_s + oo * (VV * VV) + u * VV;      // stride-25: conflict-free
            const float* xr = x3t_s + oo * JD;
            #pragma unroll 5
            for (int v = 0; v < VV; v++) {
                const float tv = tp[v];
                f2u tvv; tvv.f = make_float2(tv, tv);
                f2u m0, m1, m2, m3;                                  // broadcast LDS.64 x4
                m0.f = *reinterpret_cast<const float2*>(xr + v * TTILE + 0);
                m1.f = *reinterpret_cast<const float2*>(xr + v * TTILE + 2);
                m2.f = *reinterpret_cast<const float2*>(xr + v * TTILE + 4);
                m3.f = *reinterpret_cast<const float2*>(xr + v * TTILE + 6);
                oa2[0] = ffma2(tvv.u, m0.u, oa2[0]);
                oa2[1] = ffma2(tvv.u, m1.u, oa2[1]);
                oa2[2] = ffma2(tvv.u, m2.u, oa2[2]);
                oa2[3] = ffma2(tvv.u, m3.u, oa2[3]);
            }
            if (lane < VV) {
                const int o = obase + oo;
                float* po = out + ((size_t)(n * OC + o) * TT + t0) * VV + u;
                #pragma unroll
                for (int pr = 0; pr < 4; pr++) {
                    f2u r; r.u = oa2[pr];
                    po[(2 * pr) * VV]     = r.f.x;
                    po[(2 * pr + 1) * VV] = r.f.y;
                }
            }
        }
        // no trailing barrier: next iteration's post-A barrier covers the
        // x3t WAR hazard (Phase A doesn't touch x3t/top)
    }
}

// ============================================================
// launch
// ============================================================
extern "C" void kernel_launch(void* const* d_in, const int* in_sizes, int n_in,
                              void* d_out, int out_size) {
    const float* x  = (const float*)d_in[0];
    const float* A  = (const float*)d_in[1];
    const float* w1 = (const float*)d_in[2];
    const float* b1 = (const float*)d_in[3];
    const float* w2 = (const float*)d_in[4];
    const float* b2 = (const float*)d_in[5];
    const float* w3 = (const float*)d_in[6];
    const float* b3 = (const float*)d_in[7];
    const float* w4 = (const float*)d_in[8];
    const float* b4 = (const float*)d_in[9];
    float* out = (float*)d_out;

    cudaFuncSetAttribute(k_main, cudaFuncAttributeMaxDynamicSharedMemorySize, SMEM_BYTES);

    k_mean<<<NB * CC, 128>>>(x);
    k_top<<<NB, 256>>>(A, w1, b1, w2, b2, w4, b4);
    k_main<<<dim3(4, NB), 256, SMEM_BYTES>>>(x, w3, b3, out);
}

// round 4
// speedup vs baseline: 1.2243x; 1.2243x over previous
#include <cuda_runtime.h>
#include <cstdint>

// Problem constants
#define NB 128   // batch
#define CC 64    // in channels
#define TT 128   // time
#define VV 25    // vertices
#define RR 8     // rel channels
#define OC 64    // out channels

// ---- scratch (device globals: no allocation allowed) ----
__device__ float g_xm[NB * CC * VV];                // mean over T   (819 KB)
__device__ float g_top[(size_t)NB * OC * VV * VV];  // top tensor (20.5 MB)

// ---- cp.async helpers ----
__device__ __forceinline__ void cp_async16(uint32_t dst_smem, const void* src) {
    asm volatile("cp.async.cg.shared.global [%0], [%1], 16;" :: "r"(dst_smem), "l"(src));
}
__device__ __forceinline__ void cp_commit() {
    asm volatile("cp.async.commit_group;");
}
template <int N>
__device__ __forceinline__ void cp_wait() {
    asm volatile("cp.async.wait_group %0;" :: "n"(N));
}

// ============================================================
// K1: xm[n,c,v] = mean_t x[n,c,t,v]
// ============================================================
__global__ void k_mean(const float* __restrict__ x) {
    __shared__ float xs[TT * VV];        // 3200 floats
    __shared__ float part[4][VV];
    const int b = blockIdx.x;            // n*CC + c
    const float4* px4 = reinterpret_cast<const float4*>(x + (size_t)b * (TT * VV));
    float4* xs4 = reinterpret_cast<float4*>(xs);
    const int tid = threadIdx.x;         // 128 threads

    #pragma unroll
    for (int i = tid; i < TT * VV / 4; i += 128) xs4[i] = px4[i];
    __syncthreads();

    if (tid < 100) {
        const int v = tid % VV, q = tid / VV;   // q in [0,4)
        float s = 0.f;
        #pragma unroll
        for (int t = 0; t < 32; t++) s += xs[(q * 32 + t) * VV + v];
        part[q][v] = s;
    }
    __syncthreads();
    if (tid < VV) {
        float s = (part[0][tid] + part[1][tid]) + (part[2][tid] + part[3][tid]);
        g_xm[b * VV + tid] = s * (1.0f / TT);
    }
}

// ============================================================
// K2: top[n,o,u,v]
// ============================================================
__global__ void k_top(const float* __restrict__ A,
                      const float* __restrict__ w1, const float* __restrict__ b1,
                      const float* __restrict__ w2, const float* __restrict__ b2,
                      const float* __restrict__ w4, const float* __restrict__ b4) {
    __shared__ float xm_s[CC * VV];      // 1600
    __shared__ float x1_s[RR * VV];      // 200
    __shared__ float x2_s[RR * VV];      // 200
    __shared__ float d_s[RR * VV * VV];  // 5000
    __shared__ float w4_s[OC * RR];      // 512
    __shared__ float A_s[VV * VV];       // 625
    const int n = blockIdx.x;
    const int tid = threadIdx.x;         // 256 threads

    for (int i = tid; i < CC * VV; i += 256) xm_s[i] = g_xm[n * CC * VV + i];
    for (int i = tid; i < OC * RR; i += 256) w4_s[i] = w4[i];
    for (int i = tid; i < VV * VV; i += 256) A_s[i] = A[i];
    __syncthreads();

    if (tid < RR * VV) {
        const int r = tid / VV, v = tid % VV;
        float a1 = b1[r], a2 = b2[r];
        #pragma unroll 8
        for (int c = 0; c < CC; c++) {
            const float xv = xm_s[c * VV + v];
            a1 = fmaf(w1[r * CC + c], xv, a1);
            a2 = fmaf(w2[r * CC + c], xv, a2);
        }
        x1_s[tid] = a1;
        x2_s[tid] = a2;
    }
    __syncthreads();

    for (int i = tid; i < RR * VV * VV; i += 256) {
        const int r = i / (VV * VV), rem = i % (VV * VV);
        const int u = rem / VV, v = rem % VV;
        d_s[i] = tanhf(x1_s[r * VV + u] - x2_s[r * VV + v]);
    }
    __syncthreads();

    for (int p = tid; p < VV * VV; p += 256) {
        float dr[RR];
        #pragma unroll
        for (int r = 0; r < RR; r++) dr[r] = d_s[r * VV * VV + p];
        const float av = A_s[p];
        float* dst = g_top + (size_t)n * OC * VV * VV + p;
        #pragma unroll 4
        for (int o = 0; o < OC; o++) {
            float s = b4[o];
            #pragma unroll
            for (int r = 0; r < RR; r++) s = fmaf(w4_s[o * RR + r], dr[r], s);
            dst[o * VV * VV] = s * 1.0f /*ALPHA*/ + av;
        }
    }
}

// ============================================================
// K3 (hot): per (n, o-group of 16), cp.async 2-stage c-half pipeline
//   x3[o,t,v] = b3[o] + sum_c w3[o,c]*x[n,c,t,v]       (Phase B)
//   out[n,o,t,u] = sum_v top[n,o,u,v]*x3[o,t,v]        (Phase C)
// ============================================================
#define OO_CTA 16             // o's per CTA (4 groups)
#define TTILE  8              // timesteps per tile
#define JD     (TTILE * VV)   // 200 columns
#define CHALF  32             // channels per pipeline stage
#define HFLOATS (CHALF * JD)  // 6400 floats per half-buffer
#define NPAIR  (JD / 2)       // 100

// dynamic smem layout (in floats):
#define OFF_TOP  0                         // 16*625 = 10000
#define OFF_W3   10000                     // 16*64  = 1024
#define OFF_B3   11024                     // 16
#define OFF_X    11040                     // 2 halves * 6400 = 12800 (16B aligned)
#define OFF_X3T  23840                     // 16*200 = 3200  (16B aligned)
#define SMEM_FLOATS 27040
#define SMEM_BYTES  (SMEM_FLOATS * 4)      // 108160 B -> 2 CTAs/SM

__global__ __launch_bounds__(256, 2)
void k_main(const float* __restrict__ x, const float* __restrict__ w3,
            const float* __restrict__ b3, float* __restrict__ out) {
    extern __shared__ float sm[];
    float* top_s = sm + OFF_TOP;
    float* w3_s  = sm + OFF_W3;
    float* b3_s  = sm + OFF_B3;
    float* x_s   = sm + OFF_X;       // [2][CHALF][JD]
    float* x3t_s = sm + OFF_X3T;

    const int og  = blockIdx.x;           // 0..3
    const int n   = blockIdx.y;           // 0..127
    const int tid = threadIdx.x;          // 256
    const int obase = og * OO_CTA;

    // per-CTA constants into smem
    const float* ptop = g_top + ((size_t)n * OC + obase) * (VV * VV);
    for (int i = tid; i < OO_CTA * VV * VV; i += 256) top_s[i] = ptop[i];
    for (int i = tid; i < OO_CTA * CC; i += 256) w3_s[i] = w3[obase * CC + i];
    if (tid < OO_CTA) b3_s[tid] = b3[obase + tid];

    const int ty   = tid >> 6;            // 0..3  -> 4 o's each (warp-uniform)
    const int tx   = tid & 63;            // 0..63 -> pair columns
    const int warp = tid >> 5;            // 0..7  -> 2 o's each in Phase C
    const int lane = tid & 31;
    const int u    = (lane < VV) ? lane : 0;

    // Phase B pair assignment: pairs p0 = tx, p1 = tx+64 (valid if < 100)
    const int  p0 = tx;
    const bool v1 = (tx + 64) < NPAIR;
    const int  p1 = v1 ? (tx + 64) : 0;

    // Precompute x3t scatter offsets (x3t[oo][v][tt])
    int soff[4];
    {
        const int j0 = 2 * p0, j1 = 2 * p1;
        soff[0] = (j0 % VV) * TTILE + (j0 / VV);
        soff[1] = ((j0 + 1) % VV) * TTILE + ((j0 + 1) / VV);
        soff[2] = (j1 % VV) * TTILE + (j1 / VV);
        soff[3] = ((j1 + 1) % VV) * TTILE + ((j1 + 1) / VV);
    }

    const float4* gx4 = reinterpret_cast<const float4*>(x) + (size_t)n * (CC * TT * VV / 4);
    // per-c row stride in float4: TT*VV/4 = 800

    const uint32_t x_smem = (uint32_t)__cvta_generic_to_shared(x_s);

    // stage k (k = 2*tile + h): loads c in [h*32, h*32+32) of tile (k>>1) into buf h
    auto issue_stage = [&](int k) {
        const int h = k & 1;
        const int t4 = (k >> 1) * (TTILE * VV / 4);   // tile*50
        const uint32_t dbase = x_smem + h * (HFLOATS * 4);
        // 1600 float4 per stage / 256 threads
        #pragma unroll
        for (int ii = 0; ii < 7; ii++) {
            const int i = tid + ii * 256;
            if (i < CHALF * (JD / 4)) {
                const int cp = i / (JD / 4);           // 0..31
                const int q  = i % (JD / 4);           // 0..49
                cp_async16(dbase + (uint32_t)(cp * (JD * 4) + q * 16),
                           gx4 + (size_t)(h * CHALF + cp) * 800 + t4 + q);
            }
        }
        cp_commit();
    };

    __syncthreads();          // top/w3/b3 ready
    issue_stage(0);           // prologue

    for (int i = 0; i < TT / TTILE; i++) {
        const int t0 = i * TTILE;
        float acc[4][4];

        // ---------- half 0 (c 0..31) ----------
        issue_stage(2 * i + 1);
        cp_wait<1>();          // stage 2i arrived (buf0)
        __syncthreads();

        #pragma unroll
        for (int a = 0; a < 4; a++) {
            const float bb = b3_s[ty * 4 + a];
            #pragma unroll
            for (int jj = 0; jj < 4; jj++) acc[a][jj] = bb;
        }
        {
            const float* xb = x_s;                      // buf0
            #pragma unroll 4
            for (int cp = 0; cp < CHALF; cp++) {
                const float2 xv0 = *reinterpret_cast<const float2*>(xb + cp * JD + 2 * p0);
                const float2 xv1 = *reinterpret_cast<const float2*>(xb + cp * JD + 2 * p1);
                #pragma unroll
                for (int a = 0; a < 4; a++) {
                    const float w = w3_s[(ty * 4 + a) * CC + cp];
                    acc[a][0] = fmaf(w, xv0.x, acc[a][0]);
                    acc[a][1] = fmaf(w, xv0.y, acc[a][1]);
                    acc[a][2] = fmaf(w, xv1.x, acc[a][2]);
                    acc[a][3] = fmaf(w, xv1.y, acc[a][3]);
                }
            }
        }
        __syncthreads();       // buf0 free for stage 2i+2

        // ---------- half 1 (c 32..63) ----------
        if (2 * i + 2 < 2 * (TT / TTILE)) {
            issue_stage(2 * i + 2);
            cp_wait<1>();      // stage 2i+1 arrived (buf1)
        } else {
            cp_wait<0>();
        }
        __syncthreads();

        {
            const float* xb = x_s + HFLOATS;            // buf1
            #pragma unroll 4
            for (int cp = 0; cp < CHALF; cp++) {
                const float2 xv0 = *reinterpret_cast<const float2*>(xb + cp * JD + 2 * p0);
                const float2 xv1 = *reinterpret_cast<const float2*>(xb + cp * JD + 2 * p1);
                #pragma unroll
                for (int a = 0; a < 4; a++) {
                    const float w = w3_s[(ty * 4 + a) * CC + CHALF + cp];
                    acc[a][0] = fmaf(w, xv0.x, acc[a][0]);
                    acc[a][1] = fmaf(w, xv0.y, acc[a][1]);
                    acc[a][2] = fmaf(w, xv1.x, acc[a][2]);
                    acc[a][3] = fmaf(w, xv1.y, acc[a][3]);
                }
            }
        }

        // store transposed: x3t[oo][v][tt] so Phase C reads tt-contiguous float4
        #pragma unroll
        for (int a = 0; a < 4; a++) {
            float* dst = x3t_s + (ty * 4 + a) * JD;
            dst[soff[0]] = acc[a][0];
            dst[soff[1]] = acc[a][1];
            if (v1) {
                dst[soff[2]] = acc[a][2];
                dst[soff[3]] = acc[a][3];
            }
        }
        __syncthreads();       // buf1 free + x3t ready

        // ---------- Phase C: out[o,t,u] = sum_v top[o,u,v]*x3[o,t,v] ----------
        #pragma unroll
        for (int k2 = 0; k2 < 2; k2++) {
            const int oo = warp * 2 + k2;
            float oa[TTILE] = {0, 0, 0, 0, 0, 0, 0, 0};
            const float*  tp = top_s + oo * (VV * VV) + u * VV;    // stride-25: conflict-free
            const float4* xr = reinterpret_cast<const float4*>(x3t_s + oo * JD);
            #pragma unroll 5
            for (int v = 0; v < VV; v++) {
                const float  tv = tp[v];
                const float4 a4 = xr[v * 2];       // tt 0..3 (broadcast)
                const float4 b4 = xr[v * 2 + 1];   // tt 4..7 (broadcast)
                oa[0] = fmaf(tv, a4.x, oa[0]);
                oa[1] = fmaf(tv, a4.y, oa[1]);
                oa[2] = fmaf(tv, a4.z, oa[2]);
                oa[3] = fmaf(tv, a4.w, oa[3]);
                oa[4] = fmaf(tv, b4.x, oa[4]);
                oa[5] = fmaf(tv, b4.y, oa[5]);
                oa[6] = fmaf(tv, b4.z, oa[6]);
                oa[7] = fmaf(tv, b4.w, oa[7]);
            }
            if (lane < VV) {
                const int o = obase + oo;
                float* po = out + ((size_t)(n * OC + o) * TT + t0) * VV + u;
                #pragma unroll
                for (int tt = 0; tt < TTILE; tt++) po[tt * VV] = oa[tt];
            }
        }
        // no trailing barrier needed: next tile's post-load barrier (after
        // cp_wait) separates Phase C reads of x3t from the next x3t writes,
        // and buf overwrites are fenced by the per-half barriers above.
    }
}

// ============================================================
// launch
// ============================================================
extern "C" void kernel_launch(void* const* d_in, const int* in_sizes, int n_in,
                              void* d_out, int out_size) {
    const float* x  = (const float*)d_in[0];
    const float* A  = (const float*)d_in[1];
    const float* w1 = (const float*)d_in[2];
    const float* b1 = (const float*)d_in[3];
    const float* w2 = (const float*)d_in[4];
    const float* b2 = (const float*)d_in[5];
    const float* w3 = (const float*)d_in[6];
    const float* b3 = (const float*)d_in[7];
    const float* w4 = (const float*)d_in[8];
    const float* b4 = (const float*)d_in[9];
    float* out = (float*)d_out;

    cudaFuncSetAttribute(k_main, cudaFuncAttributeMaxDynamicSharedMemorySize, SMEM_BYTES);

    k_mean<<<NB * CC, 128>>>(x);
    k_top<<<NB, 256>>>(A, w1, b1, w2, b2, w4, b4);
    k_main<<<dim3(4, NB), 256, SMEM_BYTES>>>(x, w3, b3, out);
}

// round 6
// speedup vs baseline: 1.2604x; 1.0295x over previous
#include <cuda_runtime.h>
#include <cstdint>

// Problem constants
#define NB 128   // batch
#define CC 64    // in channels
#define TT 128   // time
#define VV 25    // vertices
#define RR 8     // rel channels
#define OC 64    // out channels

// ---- scratch (device globals: no allocation allowed) ----
__device__ float g_xm[NB * CC * VV];                // mean over T   (819 KB)
__device__ float g_top[(size_t)NB * OC * VV * VV];  // top tensor (20.5 MB)

// ---- cp.async helpers ----
__device__ __forceinline__ void cp_async16(uint32_t dst_smem, const void* src) {
    asm volatile("cp.async.cg.shared.global [%0], [%1], 16;" :: "r"(dst_smem), "l"(src));
}
__device__ __forceinline__ void cp_commit() {
    asm volatile("cp.async.commit_group;");
}
template <int N>
__device__ __forceinline__ void cp_wait() {
    asm volatile("cp.async.wait_group %0;" :: "n"(N));
}

// ============================================================
// K1: xm[n,c,v] = mean_t x[n,c,t,v]
// 2 (n,c)-rows per CTA, 256 threads, contiguous 25.6KB stage
// ============================================================
__global__ void k_mean(const float* __restrict__ x) {
    __shared__ float xs[2 * TT * VV];    // 6400 floats
    __shared__ float part[2][4][VV];
    const int b0 = blockIdx.x * 2;       // rows b0, b0+1 (contiguous in x)
    const float4* px4 = reinterpret_cast<const float4*>(x + (size_t)b0 * (TT * VV));
    float4* xs4 = reinterpret_cast<float4*>(xs);
    const int tid = threadIdx.x;         // 256 threads

    #pragma unroll
    for (int i = tid; i < 2 * TT * VV / 4; i += 256) xs4[i] = px4[i];
    __syncthreads();

    if (tid < 200) {
        const int g = tid / 100;                    // row in pair
        const int rem = tid % 100;
        const int v = rem % VV, q = rem / VV;       // q in [0,4)
        const float* base = xs + g * (TT * VV);
        float s = 0.f;
        #pragma unroll
        for (int t = 0; t < 32; t++) s += base[(q * 32 + t) * VV + v];
        part[g][q][v] = s;
    }
    __syncthreads();
    if (tid < 2 * VV) {
        const int g = tid / VV, v = tid % VV;
        float s = (part[g][0][v] + part[g][1][v]) + (part[g][2][v] + part[g][3][v]);
        g_xm[(b0 + g) * VV + v] = s * (1.0f / TT);
    }
}

// ============================================================
// K2: top[n,o,u,v]
// ============================================================
__global__ void k_top(const float* __restrict__ A,
                      const float* __restrict__ w1, const float* __restrict__ b1,
                      const float* __restrict__ w2, const float* __restrict__ b2,
                      const float* __restrict__ w4, const float* __restrict__ b4) {
    __shared__ float xm_s[CC * VV];      // 1600
    __shared__ float x1_s[RR * VV];      // 200
    __shared__ float x2_s[RR * VV];      // 200
    __shared__ float d_s[RR * VV * VV];  // 5000
    __shared__ float w4_s[OC * RR];      // 512
    __shared__ float A_s[VV * VV];       // 625
    const int n = blockIdx.x;
    const int tid = threadIdx.x;         // 256 threads

    for (int i = tid; i < CC * VV; i += 256) xm_s[i] = g_xm[n * CC * VV + i];
    for (int i = tid; i < OC * RR; i += 256) w4_s[i] = w4[i];
    for (int i = tid; i < VV * VV; i += 256) A_s[i] = A[i];
    __syncthreads();

    if (tid < RR * VV) {
        const int r = tid / VV, v = tid % VV;
        float a1 = b1[r], a2 = b2[r];
        #pragma unroll 8
        for (int c = 0; c < CC; c++) {
            const float xv = xm_s[c * VV + v];
            a1 = fmaf(w1[r * CC + c], xv, a1);
            a2 = fmaf(w2[r * CC + c], xv, a2);
        }
        x1_s[tid] = a1;
        x2_s[tid] = a2;
    }
    __syncthreads();

    for (int i = tid; i < RR * VV * VV; i += 256) {
        const int r = i / (VV * VV), rem = i % (VV * VV);
        const int u = rem / VV, v = rem % VV;
        d_s[i] = tanhf(x1_s[r * VV + u] - x2_s[r * VV + v]);
    }
    __syncthreads();

    for (int p = tid; p < VV * VV; p += 256) {
        float dr[RR];
        #pragma unroll
        for (int r = 0; r < RR; r++) dr[r] = d_s[r * VV * VV + p];
        const float av = A_s[p];
        float* dst = g_top + (size_t)n * OC * VV * VV + p;
        #pragma unroll 4
        for (int o = 0; o < OC; o++) {
            float s = b4[o];
            #pragma unroll
            for (int r = 0; r < RR; r++) s = fmaf(w4_s[o * RR + r], dr[r], s);
            dst[o * VV * VV] = s * 1.0f /*ALPHA*/ + av;
        }
    }
}

// ============================================================
// K3 (hot): per (n, o-group of 16), cp.async 2-stage c-half pipeline
//   Phase B: 8-o x 2-col register tiles, broadcast LDS.128 weights
//   Phase C: out[o,t,u] = sum_v top[o,u,v]*x3[o,t,v]
// ============================================================
#define OO_CTA 16             // o's per CTA (4 groups)
#define TTILE  8              // timesteps per tile
#define JD     (TTILE * VV)   // 200 columns
#define CHALF  32             // channels per pipeline stage
#define HFLOATS (CHALF * JD)  // 6400 floats per half-buffer
#define NPAIR  (JD / 2)       // 100

// dynamic smem layout (in floats):
#define OFF_TOP  0                         // 16*625 = 10000
#define OFF_W3T  10000                     // transposed w3 [c][16 o] = 1024
#define OFF_B3   11024                     // 16
#define OFF_X    11040                     // 2 halves * 6400 = 12800 (16B aligned)
#define OFF_X3T  23840                     // 16*200 = 3200  (16B aligned)
#define SMEM_FLOATS 27040
#define SMEM_BYTES  (SMEM_FLOATS * 4)      // 108160 B -> 2 CTAs/SM

__global__ __launch_bounds__(256, 2)
void k_main(const float* __restrict__ x, const float* __restrict__ w3,
            const float* __restrict__ b3, float* __restrict__ out) {
    extern __shared__ float sm[];
    float* top_s = sm + OFF_TOP;
    float* w3t_s = sm + OFF_W3T;     // [CC][OO_CTA]
    float* b3_s  = sm + OFF_B3;
    float* x_s   = sm + OFF_X;       // [2][CHALF][JD]
    float* x3t_s = sm + OFF_X3T;

    const int og  = blockIdx.x;           // 0..3
    const int n   = blockIdx.y;           // 0..127
    const int tid = threadIdx.x;          // 256
    const int obase = og * OO_CTA;

    // per-CTA constants into smem
    const float* ptop = g_top + ((size_t)n * OC + obase) * (VV * VV);
    for (int i = tid; i < OO_CTA * VV * VV; i += 256) top_s[i] = ptop[i];
    for (int i = tid; i < OO_CTA * CC; i += 256) {
        const int o = i / CC, c = i % CC;               // read coalesced over i
        w3t_s[c * OO_CTA + o] = w3[(obase + o) * CC + c];
    }
    if (tid < OO_CTA) b3_s[tid] = b3[obase + tid];

    // Phase B mapping: oh = o-half (8 o's), p = pair index (2 cols)
    const int oh   = tid >> 7;            // 0..1 (warp-uniform)
    const int p    = tid & 127;           // pair index; active iff p < 100
    const bool act = (p < NPAIR);
    // Phase C mapping
    const int warp = tid >> 5;            // 0..7 -> 2 o's each
    const int lane = tid & 31;
    const int u    = (lane < VV) ? lane : 0;

    // x3t scatter offsets for cols j = 2p, 2p+1  (x3t[oo][v][tt])
    const int j0 = 2 * (act ? p : 0);
    const int s0 = (j0 % VV) * TTILE + (j0 / VV);
    const int s1 = ((j0 + 1) % VV) * TTILE + ((j0 + 1) / VV);

    const float4* gx4 = reinterpret_cast<const float4*>(x) + (size_t)n * (CC * TT * VV / 4);
    // per-c row stride in float4: TT*VV/4 = 800

    const uint32_t x_smem = (uint32_t)__cvta_generic_to_shared(x_s);

    // stage k (k = 2*tile + h): loads c in [h*32, h*32+32) of tile (k>>1) into buf h
    auto issue_stage = [&](int k) {
        const int h = k & 1;
        const int t4 = (k >> 1) * (TTILE * VV / 4);   // tile*50
        const uint32_t dbase = x_smem + h * (HFLOATS * 4);
        #pragma unroll
        for (int ii = 0; ii < 7; ii++) {
            const int i = tid + ii * 256;
            if (i < CHALF * (JD / 4)) {
                const int cp = i / (JD / 4);           // 0..31
                const int q  = i % (JD / 4);           // 0..49
                cp_async16(dbase + (uint32_t)(cp * (JD * 4) + q * 16),
                           gx4 + (size_t)(h * CHALF + cp) * 800 + t4 + q);
            }
        }
        cp_commit();
    };

    __syncthreads();          // top/w3t/b3 ready
    issue_stage(0);           // prologue

    for (int i = 0; i < TT / TTILE; i++) {
        const int t0 = i * TTILE;
        float acc[8][2];

        // ---------- half 0 (c 0..31) ----------
        issue_stage(2 * i + 1);
        cp_wait<1>();          // stage 2i arrived (buf0)
        __syncthreads();

        if (act) {
            #pragma unroll
            for (int a = 0; a < 8; a++) {
                const float bb = b3_s[oh * 8 + a];
                acc[a][0] = bb;
                acc[a][1] = bb;
            }
            const float* xb = x_s;                      // buf0
            #pragma unroll 4
            for (int c = 0; c < CHALF; c++) {
                const float2 xv = *reinterpret_cast<const float2*>(xb + c * JD + 2 * p);
                const float4 wA = *reinterpret_cast<const float4*>(w3t_s + c * OO_CTA + oh * 8);
                const float4 wB = *reinterpret_cast<const float4*>(w3t_s + c * OO_CTA + oh * 8 + 4);
                acc[0][0] = fmaf(wA.x, xv.x, acc[0][0]); acc[0][1] = fmaf(wA.x, xv.y, acc[0][1]);
                acc[1][0] = fmaf(wA.y, xv.x, acc[1][0]); acc[1][1] = fmaf(wA.y, xv.y, acc[1][1]);
                acc[2][0] = fmaf(wA.z, xv.x, acc[2][0]); acc[2][1] = fmaf(wA.z, xv.y, acc[2][1]);
                acc[3][0] = fmaf(wA.w, xv.x, acc[3][0]); acc[3][1] = fmaf(wA.w, xv.y, acc[3][1]);
                acc[4][0] = fmaf(wB.x, xv.x, acc[4][0]); acc[4][1] = fmaf(wB.x, xv.y, acc[4][1]);
                acc[5][0] = fmaf(wB.y, xv.x, acc[5][0]); acc[5][1] = fmaf(wB.y, xv.y, acc[5][1]);
                acc[6][0] = fmaf(wB.z, xv.x, acc[6][0]); acc[6][1] = fmaf(wB.z, xv.y, acc[6][1]);
                acc[7][0] = fmaf(wB.w, xv.x, acc[7][0]); acc[7][1] = fmaf(wB.w, xv.y, acc[7][1]);
            }
        }
        __syncthreads();       // buf0 free for stage 2i+2

        // ---------- half 1 (c 32..63) ----------
        if (2 * i + 2 < 2 * (TT / TTILE)) {
            issue_stage(2 * i + 2);
            cp_wait<1>();      // stage 2i+1 arrived (buf1)
        } else {
            cp_wait<0>();
        }
        __syncthreads();

        if (act) {
            const float* xb = x_s + HFLOATS;            // buf1
            #pragma unroll 4
            for (int c = 0; c < CHALF; c++) {
                const float2 xv = *reinterpret_cast<const float2*>(xb + c * JD + 2 * p);
                const float4 wA = *reinterpret_cast<const float4*>(w3t_s + (CHALF + c) * OO_CTA + oh * 8);
                const float4 wB = *reinterpret_cast<const float4*>(w3t_s + (CHALF + c) * OO_CTA + oh * 8 + 4);
                acc[0][0] = fmaf(wA.x, xv.x, acc[0][0]); acc[0][1] = fmaf(wA.x, xv.y, acc[0][1]);
                acc[1][0] = fmaf(wA.y, xv.x, acc[1][0]); acc[1][1] = fmaf(wA.y, xv.y, acc[1][1]);
                acc[2][0] = fmaf(wA.z, xv.x, acc[2][0]); acc[2][1] = fmaf(wA.z, xv.y, acc[2][1]);
                acc[3][0] = fmaf(wA.w, xv.x, acc[3][0]); acc[3][1] = fmaf(wA.w, xv.y, acc[3][1]);
                acc[4][0] = fmaf(wB.x, xv.x, acc[4][0]); acc[4][1] = fmaf(wB.x, xv.y, acc[4][1]);
                acc[5][0] = fmaf(wB.y, xv.x, acc[5][0]); acc[5][1] = fmaf(wB.y, xv.y, acc[5][1]);
                acc[6][0] = fmaf(wB.z, xv.x, acc[6][0]); acc[6][1] = fmaf(wB.z, xv.y, acc[6][1]);
                acc[7][0] = fmaf(wB.w, xv.x, acc[7][0]); acc[7][1] = fmaf(wB.w, xv.y, acc[7][1]);
            }
            // store transposed: x3t[oo][v][tt]
            #pragma unroll
            for (int a = 0; a < 8; a++) {
                float* dst = x3t_s + (oh * 8 + a) * JD;
                dst[s0] = acc[a][0];
                dst[s1] = acc[a][1];
            }
        }
        __syncthreads();       // buf1 free + x3t ready

        // ---------- Phase C: out[o,t,u] = sum_v top[o,u,v]*x3[o,t,v] ----------
        #pragma unroll
        for (int k2 = 0; k2 < 2; k2++) {
            const int oo = warp * 2 + k2;
            float oa[TTILE] = {0, 0, 0, 0, 0, 0, 0, 0};
            const float*  tp = top_s + oo * (VV * VV) + u * VV;    // stride-25: conflict-free
            const float4* xr = reinterpret_cast<const float4*>(x3t_s + oo * JD);
            #pragma unroll 5
            for (int v = 0; v < VV; v++) {
                const float  tv = tp[v];
                const float4 a4 = xr[v * 2];       // tt 0..3 (broadcast)
                const float4 b4 = xr[v * 2 + 1];   // tt 4..7 (broadcast)
                oa[0] = fmaf(tv, a4.x, oa[0]);
                oa[1] = fmaf(tv, a4.y, oa[1]);
                oa[2] = fmaf(tv, a4.z, oa[2]);
                oa[3] = fmaf(tv, a4.w, oa[3]);
                oa[4] = fmaf(tv, b4.x, oa[4]);
                oa[5] = fmaf(tv, b4.y, oa[5]);
                oa[6] = fmaf(tv, b4.z, oa[6]);
                oa[7] = fmaf(tv, b4.w, oa[7]);
            }
            if (lane < VV) {
                const int o = obase + oo;
                float* po = out + ((size_t)(n * OC + o) * TT + t0) * VV + u;
                #pragma unroll
                for (int tt = 0; tt < TTILE; tt++) po[tt * VV] = oa[tt];
            }
        }
        // no trailing barrier: next tile's post-wait barrier fences x3t WAR.
    }
}

// ============================================================
// launch
// ============================================================
extern "C" void kernel_launch(void* const* d_in, const int* in_sizes, int n_in,
                              void* d_out, int out_size) {
    const float* x  = (const float*)d_in[0];
    const float* A  = (const float*)d_in[1];
    const float* w1 = (const float*)d_in[2];
    const float* b1 = (const float*)d_in[3];
    const float* w2 = (const float*)d_in[4];
    const float* b2 = (const float*)d_in[5];
    const float* w3 = (const float*)d_in[6];
    const float* b3 = (const float*)d_in[7];
    const float* w4 = (const float*)d_in[8];
    const float* b4 = (const float*)d_in[9];
    float* out = (float*)d_out;

    cudaFuncSetAttribute(k_main, cudaFuncAttributeMaxDynamicSharedMemorySize, SMEM_BYTES);

    k_mean<<<NB * CC / 2, 256>>>(x);
    k_top<<<NB, 256>>>(A, w1, b1, w2, b2, w4, b4);
    k_main<<<dim3(4, NB), 256, SMEM_BYTES>>>(x, w3, b3, out);
}